// round 2
// baseline (speedup 1.0000x reference)
#include <cuda_runtime.h>
#include <math.h>
#include <stdint.h>

#define NN 262144
#define DD 16
#define KK 64
#define TAUF 0.1f
#define DLOG2PI 1.8378770664093454835
#define L2E 1.4426950408889634f
#define LN2 0.6931471805599453f

#define MAIN_GRID 1024
#define MAIN_BLOCK 256
#define WARPS_PER_BLOCK 8
#define MM_GRID 2048

// ---------------- device globals (no dynamic allocation) ----------------
__device__ float g_w[KK][DD];     // log2e * exp(-r_k) * mu_k[d]
__device__ float g_alpha2[KK];    // log2e * (-0.5*exp(-r_k))
__device__ float g_cc2[KK];       // log2e * (alpha*||mu_k||^2 + beta_k)
__device__ float g_logpi[KK];     // natural log_softmax(pi)
__device__ float g_logpi2[KK];    // log2e * logpi
__device__ float g_sumlogpi;
__device__ unsigned g_minkey[DD];
__device__ unsigned g_maxkey[DD];
__device__ float g_partial[MAIN_GRID];

// ---------------- helpers ----------------
__device__ __forceinline__ unsigned fkey(float f) {
    unsigned u = __float_as_uint(f);
    return (u & 0x80000000u) ? ~u : (u | 0x80000000u);
}
__device__ __forceinline__ float fdec(unsigned k) {
    unsigned u = (k & 0x80000000u) ? (k & 0x7FFFFFFFu) : ~k;
    return __uint_as_float(u);
}

// ---------------- kernel 1: per-k constants + logpi + minmax init ----------------
__global__ void prep_kernel(const float* __restrict__ mu,
                            const float* __restrict__ pi,
                            const float* __restrict__ rv) {
    __shared__ float sh[KK];
    int t = threadIdx.x;          // 64 threads
    float p = pi[t];
    sh[t] = p; __syncthreads();
    for (int s = 32; s; s >>= 1) { if (t < s) sh[t] = fmaxf(sh[t], sh[t + s]); __syncthreads(); }
    float m = sh[0]; __syncthreads();
    sh[t] = __expf(p - m); __syncthreads();
    for (int s = 32; s; s >>= 1) { if (t < s) sh[t] += sh[t + s]; __syncthreads(); }
    float lse = m + __logf(sh[0]); __syncthreads();
    float lp = p - lse;
    g_logpi[t]  = lp;
    g_logpi2[t] = lp * L2E;
    sh[t] = lp; __syncthreads();
    for (int s = 32; s; s >>= 1) { if (t < s) sh[t] += sh[t + s]; __syncthreads(); }
    if (t == 0) g_sumlogpi = sh[0];

    float rk = rv[t];
    float ie = __expf(-rk);               // 1/exp(r_k)
    float msq = 0.f;
#pragma unroll
    for (int d = 0; d < DD; d++) {
        float md = mu[t * DD + d];
        g_w[t][d] = L2E * ie * md;
        msq = fmaf(md, md, msq);
    }
    float alpha = -0.5f * ie;
    float beta  = -0.5f * 16.f * (rk + (float)DLOG2PI);
    g_alpha2[t] = L2E * alpha;
    g_cc2[t]    = L2E * fmaf(alpha, msq, beta);

    if (t < DD) { g_minkey[t] = 0xFFFFFFFFu; g_maxkey[t] = 0u; }
}

// ---------------- kernel 2: per-dim min/max of met_locs ----------------
__global__ void __launch_bounds__(256) minmax_kernel(const float4* __restrict__ met4) {
    const int n4 = NN * DD / 4;
    int t = blockIdx.x * blockDim.x + threadIdx.x;
    int stride = gridDim.x * blockDim.x;      // multiple of 4 -> phase fixed
    float4 mn = make_float4(3.4e38f, 3.4e38f, 3.4e38f, 3.4e38f);
    float4 mx = make_float4(-3.4e38f, -3.4e38f, -3.4e38f, -3.4e38f);
    for (int i = t; i < n4; i += stride) {
        float4 v = met4[i];
        mn.x = fminf(mn.x, v.x); mx.x = fmaxf(mx.x, v.x);
        mn.y = fminf(mn.y, v.y); mx.y = fmaxf(mx.y, v.y);
        mn.z = fminf(mn.z, v.z); mx.z = fmaxf(mx.z, v.z);
        mn.w = fminf(mn.w, v.w); mx.w = fmaxf(mx.w, v.w);
    }
    int d0 = (t & 3) * 4;
    atomicMin(&g_minkey[d0 + 0], fkey(mn.x)); atomicMax(&g_maxkey[d0 + 0], fkey(mx.x));
    atomicMin(&g_minkey[d0 + 1], fkey(mn.y)); atomicMax(&g_maxkey[d0 + 1], fkey(mx.y));
    atomicMin(&g_minkey[d0 + 2], fkey(mn.z)); atomicMax(&g_maxkey[d0 + 2], fkey(mx.z));
    atomicMin(&g_minkey[d0 + 3], fkey(mn.w)); atomicMax(&g_maxkey[d0 + 3], fkey(mx.w));
}

// ---------------- kernel 3: z-loss (warp per row, lane owns k=2l,2l+1) ----------------
__global__ void __launch_bounds__(MAIN_BLOCK) zloss_kernel(const float* __restrict__ met,
                                                           const float* __restrict__ z) {
    const int lane = threadIdx.x & 31;
    const int warp = threadIdx.x >> 5;
    const int gwarp = blockIdx.x * WARPS_PER_BLOCK + warp;
    const int totw = MAIN_GRID * WARPS_PER_BLOCK;

    const int k0 = 2 * lane;
    float w0[DD], w1[DD];
#pragma unroll
    for (int d = 0; d < DD; d++) { w0[d] = g_w[k0][d]; w1[d] = g_w[k0 + 1][d]; }
    const float a0 = g_alpha2[k0], a1 = g_alpha2[k0 + 1];
    const float c0 = g_cc2[k0],    c1 = g_cc2[k0 + 1];
    const float lp0 = g_logpi2[k0], lp1 = g_logpi2[k0 + 1];

    float accT = 0.f;     // lane 0 only: sum of nonlinear per-row terms (natural log units)
    float acc_sz = 0.f;   // per-lane: sum of raw z (linear term, deferred reduce)

    for (int row = gwarp; row < NN; row += totw) {
        const float4* xp = reinterpret_cast<const float4*>(met + (size_t)row * DD);
        float4 qa = xp[0], qb = xp[1], qc = xp[2], qd = xp[3];
        float x[DD] = { qa.x, qa.y, qa.z, qa.w, qb.x, qb.y, qb.z, qb.w,
                        qc.x, qc.y, qc.z, qc.w, qd.x, qd.y, qd.z, qd.w };
        const float2 zz = *reinterpret_cast<const float2*>(z + (size_t)row * KK + 2 * lane);

        float d0 = c0, d1 = c1, xs = 0.f;
#pragma unroll
        for (int d = 0; d < DD; d++) {
            d0 = fmaf(x[d], w0[d], d0);
            d1 = fmaf(x[d], w1[d], d1);
            xs = fmaf(x[d], x[d], xs);
        }
        float l0 = fmaf(a0, xs, d0);      // logN_k in log2 units
        float l1 = fmaf(a1, xs, d1);

        float z0 = zz.x, z1 = zz.y;
        float z02 = z0 * L2E, z12 = z1 * L2E;
        float v0 = z02 + l0, v1 = z12 + l1;
        float u0 = fmaf(-TAUF, z02, lp0), u1 = fmaf(-TAUF, z12, lp1);

        float mz = fmaxf(z02, z12);
        float mv = fmaxf(v0, v1);
        float mq = fmaxf(u0, u1);
#pragma unroll
        for (int off = 16; off; off >>= 1) {
            mz = fmaxf(mz, __shfl_xor_sync(0xffffffffu, mz, off));
            mv = fmaxf(mv, __shfl_xor_sync(0xffffffffu, mv, off));
            mq = fmaxf(mq, __shfl_xor_sync(0xffffffffu, mq, off));
        }

        float ez = exp2f(z02 - mz) + exp2f(z12 - mz);
        float ev = exp2f(v0 - mv) + exp2f(v1 - mv);
        float eu = exp2f(u0 - mq) + exp2f(u1 - mq);
#pragma unroll
        for (int off = 16; off; off >>= 1) {
            ez += __shfl_xor_sync(0xffffffffu, ez, off);
            ev += __shfl_xor_sync(0xffffffffu, ev, off);
            eu += __shfl_xor_sync(0xffffffffu, eu, off);
        }
        acc_sz += z0 + z1;

        if (lane == 0) {
            float lz = mz + __log2f(ez);   // lse_z / ln2
            float lv = mv + __log2f(ev);   // lse(z+logN) / ln2
            float lu = mq + __log2f(eu);   // lse(logpi - tau z) / ln2
            accT += LN2 * fmaf(63.f, lz, fmaf(-64.f, lu, lv));
        }
    }

#pragma unroll
    for (int off = 16; off; off >>= 1)
        acc_sz += __shfl_xor_sync(0xffffffffu, acc_sz, off);

    __shared__ float sred[WARPS_PER_BLOCK];
    if (lane == 0) sred[warp] = fmaf(-(TAUF + 1.f), acc_sz, accT);
    __syncthreads();
    if (threadIdx.x == 0) {
        float s = 0.f;
#pragma unroll
        for (int i = 0; i < WARPS_PER_BLOCK; i++) s += sred[i];
        g_partial[blockIdx.x] = s;
    }
}

// ---------------- kernel 4: small losses + final sum (double) ----------------
__global__ void final_kernel(const float* __restrict__ mu,
                             const float* __restrict__ lambda_mu,
                             const float* __restrict__ b,
                             const float* __restrict__ Cv,
                             const float* __restrict__ rv,
                             float* __restrict__ out) {
    __shared__ float shR[DD];
    __shared__ double sred[256];
    int t = threadIdx.x;
    if (t < DD) shR[t] = fdec(g_maxkey[t]) - fdec(g_minkey[t]);
    __syncthreads();

    double R2 = 0.0;
#pragma unroll
    for (int d = 0; d < DD; d++) R2 += (double)shR[d] * (double)shR[d];
    const double cc = 5.0, gg = 4.0;                 // c = 1.25+15/4, g = 0.25+15/4
    const double G  = cc / (50.0 * gg) * sqrt(R2);

    double acc = 0.0;
    // mu quadratic + b quadratic over K*D
    for (int i = t; i < KK * DD; i += blockDim.x) {
        int d = i & (DD - 1);
        double lam = (double)lambda_mu[d];
        double var = lam * lam * (double)shR[d];
        double diff = (double)mu[i] - (double)b[i];
        double bb = (double)b[i];
        acc += 0.5 * diff * diff / var + 0.5 * bb * bb;
    }
    // per-dim: mu logdet (K/2 * log var each) + lambda prior
    for (int d = t; d < DD; d += blockDim.x) {
        double lam = (double)lambda_mu[d];
        double var = lam * lam * (double)shR[d];
        acc += 0.5 * (double)KK * log(var);
        acc -= 0.5 * log(0.5) - lgamma(0.5) - 0.5 * lam - 0.5 * exp(lam);
    }
    // per-k: r prior (Gamma(c, rate=C)) + C prior (Gamma(g, rate=G))
    for (int k = t; k < KK; k += blockDim.x) {
        double rk = (double)rv[k], Ck = (double)Cv[k];
        acc -= cc * log(Ck) - (cc - 1.0) * rk - Ck * exp(-rk) - lgamma(cc);
        acc -= gg * log(G)  - (gg - 1.0) * Ck - G  * exp(-Ck) - lgamma(gg);
    }
    // z-loss partials
    for (int i = t; i < MAIN_GRID; i += blockDim.x) acc -= (double)g_partial[i];

    if (t == 0) {
        double sumlp = (double)g_sumlogpi;
        double G0 = lgamma(64.0) + 63.0 * log(0.1) + sumlp;   // per-row constant in con
        acc -= (double)NN * G0;                               // z-loss constant part
        acc += (63.0 / 64.0) * sumlp;                         // pi_loss
        acc += (double)KK * 0.5 * (double)DD * DLOG2PI;       // mu_loss const
        acc += 0.5 * (double)KK * (double)DD * DLOG2PI;       // b_loss const
    }

    sred[t] = acc; __syncthreads();
    for (int s = 128; s; s >>= 1) { if (t < s) sred[t] += sred[t + s]; __syncthreads(); }
    if (t == 0) out[0] = (float)sred[0];
}

// ---------------- launch ----------------
extern "C" void kernel_launch(void* const* d_in, const int* in_sizes, int n_in,
                              void* d_out, int out_size) {
    const float* met = (const float*)d_in[0];
    const float* mu  = (const float*)d_in[1];
    const float* pi  = (const float*)d_in[2];
    const float* lam = (const float*)d_in[3];
    const float* b   = (const float*)d_in[4];
    const float* C   = (const float*)d_in[5];
    const float* r   = (const float*)d_in[6];
    const float* z   = (const float*)d_in[7];
    (void)in_sizes; (void)n_in; (void)out_size;

    prep_kernel<<<1, 64>>>(mu, pi, r);
    minmax_kernel<<<MM_GRID, 256>>>(reinterpret_cast<const float4*>(met));
    zloss_kernel<<<MAIN_GRID, MAIN_BLOCK>>>(met, z);
    final_kernel<<<1, 256>>>(mu, lam, b, C, r, (float*)d_out);
}